// round 11
// baseline (speedup 1.0000x reference)
#include <cuda_runtime.h>

// Fixed shapes: B=64, P=68, H=W=64 -> 4352 tiles of 4096 pixels
#define HW       4096
#define NTHREADS 256
#define NWARPS   8
#define EPS      1e-5f
#define LOG2E    1.4426950408889634f
#define LN2      0.6931471805599453f

__device__ __forceinline__ float ex2(float x) {
    float r; asm("ex2.approx.ftz.f32 %0, %1;" : "=f"(r) : "f"(x)); return r;
}
__device__ __forceinline__ float lg2(float x) {
    float r; asm("lg2.approx.f32 %0, %1;" : "=f"(r) : "f"(x)); return r;
}

// Cross-block accumulator: zero at entry; last block restores zero (replay-safe).
__device__ float        g_partial = 0.0f;
__device__ unsigned int g_count   = 0u;

__global__ __launch_bounds__(NTHREADS)
void gauss_kl_kernel(const float* __restrict__ hm,
                     const float* __restrict__ means,
                     const float* __restrict__ cov,
                     float* __restrict__ out,
                     float inv_rows)
{
    const int bp  = blockIdx.x;
    const int tid = threadIdx.x;

    // Front-batch the 4 streaming LDG.128 loads (latency hidden under pass 1)
    const float4* hm4 = reinterpret_cast<const float4*>(hm + (size_t)bp * HW);
    float4 h[4];
#pragma unroll
    for (int k = 0; k < 4; k++) h[k] = __ldcs(&hm4[tid + k * NTHREADS]);

    // Per-tile Gaussian parameters
    const float mx  = __ldg(&means[bp * 2 + 0]);
    const float my  = __ldg(&means[bp * 2 + 1]);
    const float s00 = __ldg(&cov[bp * 4 + 0]);
    const float s01 = __ldg(&cov[bp * 4 + 1]);
    const float s10 = __ldg(&cov[bp * 4 + 2]);
    const float s11 = __ldg(&cov[bp * 4 + 3]);
    const float det = fmaf(s00, s11, -s01 * s10) + EPS;
    const float inv_det = LOG2E / det;
    // lp = log2(exp(-quad/2)) = Ac*dx^2 + Bc*dx*dy + Cc*dy^2   (<= 0)
    const float Ac = -0.5f * s11 * inv_det;
    const float Bc =  0.5f * (s01 + s10) * inv_det;
    const float Cc = -0.5f * s00 * inv_det;
    // Completed square: max over dx of lp(row) = C'*dy^2, C' = -log2e/(2*s11).
    // => 1/C' = -2*ln2*s11 (no division needed). Thresholds on dy^2:
    const float rCp = -(2.0f * LN2) * s11;        // 1/C' (negative)
    const float TH2 = -30.0f * rCp;               // d2 >= TH2 -> all lp < -30 (deep)

    // Geometry: i4 = tid + 256k -> row = (tid>>4) + 16k, x0 = (tid&15)*4
    const float xm  = (float)((tid & 15) << 2) - mx;
    const float dx0 = xm,        dx1 = xm + 1.0f;
    const float dx2 = xm + 2.0f, dx3 = xm + 3.0f;
    const float dyb = (float)(tid >> 4) - my;
    // Warp-uniform row pair for zone tests: rows {2*wid, 2*wid+1} + 16k
    const int   wid = tid >> 5, lid = tid & 31;
    const float dwA = (float)(2 * wid) - my;      // + 16k per group

    // Pass 1: e = 2^lp where any row pixel can matter; deep rows skip EX2.
    float e[16];
    float S = 0.0f;
#pragma unroll
    for (int k = 0; k < 4; k++) {
        const float dA = dwA + (float)(16 * k);
        const float dB = dA + 1.0f;
        const float d2 = fminf(dA * dA, dB * dB);  // warp-uniform
        if (d2 < TH2) {
            const float dy   = dyb + (float)(16 * k);
            const float bdy  = Bc * dy;
            const float cdy2 = (Cc * dy) * dy;
            const float e0 = ex2(fmaf(fmaf(Ac, dx0, bdy), dx0, cdy2));
            const float e1 = ex2(fmaf(fmaf(Ac, dx1, bdy), dx1, cdy2));
            const float e2 = ex2(fmaf(fmaf(Ac, dx2, bdy), dx2, cdy2));
            const float e3 = ex2(fmaf(fmaf(Ac, dx3, bdy), dx3, cdy2));
            e[4*k+0] = e0; e[4*k+1] = e1; e[4*k+2] = e2; e[4*k+3] = e3;
            S += (e0 + e1) + (e2 + e3);
        } else {
            // deep tail: every e < 2^-30; contribution to S < 4e-6 relative
            e[4*k+0] = 0.0f; e[4*k+1] = 0.0f; e[4*k+2] = 0.0f; e[4*k+3] = 0.0f;
        }
    }

    // Reduce S: warp shfl, lane0 -> smem, ONE barrier, all threads sum partials
    __shared__ float ws[NWARPS];
    __shared__ float wa[NWARPS];
#pragma unroll
    for (int o = 16; o > 0; o >>= 1) S += __shfl_xor_sync(0xffffffffu, S, o);
    if (lid == 0) ws[wid] = S;
    __syncthreads();
    const float Sfull = ((ws[0] + ws[1]) + (ws[2] + ws[3]))
                      + ((ws[4] + ws[5]) + (ws[6] + ws[7]));
    const float c   = EPS * Sfull;               // pr + eps = (e + c)/S
    const float lgc = lg2(c);
    const float K   = __fdividef(LOG2E, c);      // Taylor slope: lg2(c+e) ~ lgc + K*e
    // live iff some row pixel has lp > lgc - 6  <=>  d2 < TH1
    const float TH1 = (lgc - 6.0f) * rCp;        // rCp < 0, (lgc-6) < 0 -> TH1 > 0

    // Pass 2: acc = sum hm * (lg2(hm) - lg2(e + c)); tail groups use the
    // 1-term Taylor lg2(e+c) ~= lgc + K*e (error < 1.8e-4 bits), deep e==0.
    float acc = 0.0f;
#pragma unroll
    for (int k = 0; k < 4; k++) {
        const float4 hv = h[k];
        const float lh0 = lg2(hv.x), lh1 = lg2(hv.y);
        const float lh2 = lg2(hv.z), lh3 = lg2(hv.w);
        const float dA = dwA + (float)(16 * k);
        const float dB = dA + 1.0f;
        const float d2 = fminf(dA * dA, dB * dB);  // warp-uniform
        if (d2 < TH1) {
            acc = fmaf(hv.x, lh0 - lg2(e[4*k+0] + c), acc);
            acc = fmaf(hv.y, lh1 - lg2(e[4*k+1] + c), acc);
            acc = fmaf(hv.z, lh2 - lg2(e[4*k+2] + c), acc);
            acc = fmaf(hv.w, lh3 - lg2(e[4*k+3] + c), acc);
        } else {
            acc = fmaf(hv.x, lh0 - fmaf(e[4*k+0], K, lgc), acc);
            acc = fmaf(hv.y, lh1 - fmaf(e[4*k+1], K, lgc), acc);
            acc = fmaf(hv.z, lh2 - fmaf(e[4*k+2], K, lgc), acc);
            acc = fmaf(hv.w, lh3 - fmaf(e[4*k+3], K, lgc), acc);
        }
    }

    // Reduce acc; tid0 adds tile value into device scratch (no memset launch)
#pragma unroll
    for (int o = 16; o > 0; o >>= 1) acc += __shfl_xor_sync(0xffffffffu, acc, o);
    if (lid == 0) wa[wid] = acc;
    __syncthreads();
    if (tid == 0) {
        const float v = ((wa[0] + wa[1]) + (wa[2] + wa[3]))
                      + ((wa[4] + wa[5]) + (wa[6] + wa[7]));
        // loss_tile = ln2 * (acc + lg2(S))   [sum(hm) == 1 per tile]
        const float tile = (LN2 * inv_rows) * (v + lg2(Sfull));
        atomicAdd(&g_partial, tile);
        __threadfence();
        const unsigned old = atomicAdd(&g_count, 1u);
        if (old == gridDim.x - 1) {          // last block finalizes + resets
            __threadfence();
            out[0]    = g_partial;
            g_partial = 0.0f;
            g_count   = 0u;
        }
    }
}

extern "C" void kernel_launch(void* const* d_in, const int* in_sizes, int n_in,
                              void* d_out, int out_size)
{
    const float* hm    = (const float*)d_in[0];   // [B,P,H,W]
    const float* means = (const float*)d_in[1];   // [B,P,2]
    const float* cov   = (const float*)d_in[2];   // [B,P,4]
    float* out = (float*)d_out;

    const int n_bp = in_sizes[1] / 2;             // 4352

    gauss_kl_kernel<<<n_bp, NTHREADS>>>(hm, means, cov, out, 1.0f / (float)n_bp);
}

// round 12
// speedup vs baseline: 1.1792x; 1.1792x over previous
#include <cuda_runtime.h>

// Fixed shapes: B=64, P=68, H=W=64 -> 4352 tiles of 4096 pixels
#define HW       4096
#define NTHREADS 256
#define NWARPS   8
#define EPS      1e-5f
#define LOG2E    1.4426950408889634f
#define LN2      0.6931471805599453f

// Raw MUFU intrinsics (exp2f/log2f are PRECISE libm without -use_fast_math)
__device__ __forceinline__ float ex2(float x) {
    float r; asm("ex2.approx.ftz.f32 %0, %1;" : "=f"(r) : "f"(x)); return r;
}
__device__ __forceinline__ float lg2(float x) {
    float r; asm("lg2.approx.f32 %0, %1;" : "=f"(r) : "f"(x)); return r;
}

// Cross-block accumulator: zero at entry; last block restores zero (replay-safe).
__device__ float        g_partial = 0.0f;
__device__ unsigned int g_count   = 0u;

__global__ __launch_bounds__(NTHREADS)
void gauss_kl_kernel(const float* __restrict__ hm,
                     const float2* __restrict__ means,  // [B*P] float2
                     const float4* __restrict__ cov,    // [B*P] float4
                     float* __restrict__ out,
                     float scale)                       // LN2 / n_tiles
{
    __shared__ float4 wred[4];                          // [0:2)=S partials, [2:4)=acc
    float* ws = (float*)&wred[0];
    float* wa = (float*)&wred[2];

    const int bp  = blockIdx.x;
    const int tid = threadIdx.x;

    // Front-batch the 4 streaming LDG.128 loads (latency hidden under pass 1)
    const float4* hm4 = reinterpret_cast<const float4*>(hm + (size_t)bp * HW);
    float4 h[4];
#pragma unroll
    for (int k = 0; k < 4; k++) h[k] = __ldcs(&hm4[tid + k * NTHREADS]);

    // Per-tile Gaussian parameters: ONE LDG.64 + ONE LDG.128
    const float2 mn = __ldg(&means[bp]);
    const float4 sg = __ldg(&cov[bp]);
    const float det = fmaf(sg.x, sg.w, -sg.y * sg.z) + EPS;
    const float inv_det = LOG2E / det;
    // lp = log2(exp(-quad/2)) = Ac*dx^2 + Bc*dx*dy + Cc*dy^2
    const float Ac = -0.5f * sg.w * inv_det;
    const float Bc =  0.5f * (sg.y + sg.z) * inv_det;
    const float Cc = -0.5f * sg.x * inv_det;

    // Geometry: i4 = tid + 256k -> row = (tid>>4) + 16k, x0 = (tid&15)*4
    const float xm  = (float)((tid & 15) << 2) - mn.x;
    const float dx0 = xm,        dx1 = xm + 1.0f;
    const float dx2 = xm + 2.0f, dx3 = xm + 3.0f;
    const float dyb = (float)(tid >> 4) - mn.y;

    // Pass 1: e = 2^lp (EX2), S = pairwise sum
    float e[16];
    float S = 0.0f;
#pragma unroll
    for (int k = 0; k < 4; k++) {
        const float dy   = dyb + (float)(16 * k);
        const float bdy  = Bc * dy;
        const float cdy2 = (Cc * dy) * dy;
        const float e0 = ex2(fmaf(fmaf(Ac, dx0, bdy), dx0, cdy2));
        const float e1 = ex2(fmaf(fmaf(Ac, dx1, bdy), dx1, cdy2));
        const float e2 = ex2(fmaf(fmaf(Ac, dx2, bdy), dx2, cdy2));
        const float e3 = ex2(fmaf(fmaf(Ac, dx3, bdy), dx3, cdy2));
        e[4*k+0] = e0; e[4*k+1] = e1; e[4*k+2] = e2; e[4*k+3] = e3;
        S += (e0 + e1) + (e2 + e3);
    }

    // Reduce S: warp shfl, lane0 -> smem, ONE barrier, vector re-read
    const int wid = tid >> 5, lid = tid & 31;
#pragma unroll
    for (int o = 16; o > 0; o >>= 1) S += __shfl_xor_sync(0xffffffffu, S, o);
    if (lid == 0) ws[wid] = S;
    __syncthreads();
    const float4 w0 = wred[0], w1 = wred[1];            // 2x LDS.128
    const float Sfull = ((w0.x + w0.y) + (w0.z + w0.w))
                      + ((w1.x + w1.y) + (w1.z + w1.w));
    const float c = EPS * Sfull;                        // pr + eps = (e + c)/S

    // Pass 2 (registers only): acc = sum hm * (lg2(hm) - lg2(e + c))
    float acc = 0.0f;
#pragma unroll
    for (int k = 0; k < 4; k++) {
        const float4 hv = h[k];
        acc = fmaf(hv.x, lg2(hv.x) - lg2(e[4*k+0] + c), acc);
        acc = fmaf(hv.y, lg2(hv.y) - lg2(e[4*k+1] + c), acc);
        acc = fmaf(hv.z, lg2(hv.z) - lg2(e[4*k+2] + c), acc);
        acc = fmaf(hv.w, lg2(hv.w) - lg2(e[4*k+3] + c), acc);
    }

    // Reduce acc; tid0 adds tile value into device scratch (no memset launch)
#pragma unroll
    for (int o = 16; o > 0; o >>= 1) acc += __shfl_xor_sync(0xffffffffu, acc, o);
    if (lid == 0) wa[wid] = acc;
    __syncthreads();
    if (tid == 0) {
        const float4 a0 = wred[2], a1 = wred[3];
        const float v = ((a0.x + a0.y) + (a0.z + a0.w))
                      + ((a1.x + a1.y) + (a1.z + a1.w));
        // loss_tile = ln2 * (acc + lg2(S))   [sum(hm) == 1 per tile]
        const float tile = scale * (v + lg2(Sfull));
        atomicAdd(&g_partial, tile);
        __threadfence();
        const unsigned old = atomicAdd(&g_count, 1u);
        if (old == gridDim.x - 1) {          // last block finalizes + resets
            __threadfence();
            out[0]    = g_partial;
            g_partial = 0.0f;
            g_count   = 0u;
        }
    }
}

extern "C" void kernel_launch(void* const* d_in, const int* in_sizes, int n_in,
                              void* d_out, int out_size)
{
    const float*  hm    = (const float*)d_in[0];   // [B,P,H,W]
    const float2* means = (const float2*)d_in[1];  // [B,P,2] -> float2
    const float4* cov   = (const float4*)d_in[2];  // [B,P,4] -> float4
    float* out = (float*)d_out;

    const int n_bp = in_sizes[1] / 2;              // 4352

    gauss_kl_kernel<<<n_bp, NTHREADS>>>(hm, means, cov, out,
                                        LN2 / (float)n_bp);
}

// round 13
// speedup vs baseline: 1.2429x; 1.0540x over previous
#include <cuda_runtime.h>

// Fixed shapes: B=64, P=68, H=W=64 -> 4352 tiles of 4096 pixels
#define HW       4096
#define NTHREADS 256
#define NWARPS   8
#define EPS      1e-5f
#define LOG2E    1.4426950408889634f
#define LN2      0.6931471805599453f

// Raw MUFU intrinsics (exp2f/log2f are PRECISE libm without -use_fast_math)
__device__ __forceinline__ float ex2(float x) {
    float r; asm("ex2.approx.ftz.f32 %0, %1;" : "=f"(r) : "f"(x)); return r;
}
__device__ __forceinline__ float lg2(float x) {
    float r; asm("lg2.approx.f32 %0, %1;" : "=f"(r) : "f"(x)); return r;
}

__global__ __launch_bounds__(NTHREADS)
void gauss_kl_kernel(const float* __restrict__ hm,
                     const float2* __restrict__ means,  // [B*P] float2
                     const float4* __restrict__ cov,    // [B*P] float4
                     float* __restrict__ out,
                     float scale)                       // LN2 / n_tiles
{
    // e values live in SMEM, not registers -> no register spills.
    __shared__ float4 se[4][NTHREADS];                  // 16 KB
    __shared__ float  ws[NWARPS];
    __shared__ float  wa[NWARPS];

    const int bp  = blockIdx.x;
    const int tid = threadIdx.x;

    // Front-batch the 4 streaming LDG.128 loads (latency hidden under pass 1)
    const float4* hm4 = reinterpret_cast<const float4*>(hm + (size_t)bp * HW);
    float4 h[4];
#pragma unroll
    for (int k = 0; k < 4; k++) h[k] = __ldcs(&hm4[tid + k * NTHREADS]);

    // Per-tile Gaussian parameters: ONE LDG.64 + ONE LDG.128
    const float2 mn = __ldg(&means[bp]);
    const float4 sg = __ldg(&cov[bp]);
    const float det = fmaf(sg.x, sg.w, -sg.y * sg.z) + EPS;
    const float inv_det = LOG2E / det;
    // lp = log2(exp(-quad/2)) = Ac*dx^2 + Bc*dx*dy + Cc*dy^2
    const float Ac = -0.5f * sg.w * inv_det;
    const float Bc =  0.5f * (sg.y + sg.z) * inv_det;
    const float Cc = -0.5f * sg.x * inv_det;

    // Geometry: i4 = tid + 256k -> row = (tid>>4) + 16k, x0 = (tid&15)*4
    const float xm  = (float)((tid & 15) << 2) - mn.x;
    const float dx0 = xm,        dx1 = xm + 1.0f;
    const float dx2 = xm + 2.0f, dx3 = xm + 3.0f;
    const float dyb = (float)(tid >> 4) - mn.y;

    // Pass 1: e = 2^lp (EX2) -> STS.128 to smem; S = pairwise sum
    float S = 0.0f;
#pragma unroll
    for (int k = 0; k < 4; k++) {
        const float dy   = dyb + (float)(16 * k);
        const float bdy  = Bc * dy;
        const float cdy2 = (Cc * dy) * dy;
        float4 ev;
        ev.x = ex2(fmaf(fmaf(Ac, dx0, bdy), dx0, cdy2));
        ev.y = ex2(fmaf(fmaf(Ac, dx1, bdy), dx1, cdy2));
        ev.z = ex2(fmaf(fmaf(Ac, dx2, bdy), dx2, cdy2));
        ev.w = ex2(fmaf(fmaf(Ac, dx3, bdy), dx3, cdy2));
        se[k][tid] = ev;                     // conflict-free STS.128
        S += (ev.x + ev.y) + (ev.z + ev.w);
    }

    // Reduce S: warp shfl, lane0 -> smem, ONE barrier, all threads sum partials
    const int wid = tid >> 5, lid = tid & 31;
#pragma unroll
    for (int o = 16; o > 0; o >>= 1) S += __shfl_xor_sync(0xffffffffu, S, o);
    if (lid == 0) ws[wid] = S;
    __syncthreads();
    const float Sfull = ((ws[0] + ws[1]) + (ws[2] + ws[3]))
                      + ((ws[4] + ws[5]) + (ws[6] + ws[7]));
    const float c = EPS * Sfull;             // pr + eps = (e + c)/S

    // Pass 2: acc = sum hm * (lg2(hm) - lg2(e + c));  e re-read via LDS.128
    float acc = 0.0f;
#pragma unroll
    for (int k = 0; k < 4; k++) {
        const float4 hv = h[k];
        const float4 ev = se[k][tid];
        acc = fmaf(hv.x, lg2(hv.x) - lg2(ev.x + c), acc);
        acc = fmaf(hv.y, lg2(hv.y) - lg2(ev.y + c), acc);
        acc = fmaf(hv.z, lg2(hv.z) - lg2(ev.z + c), acc);
        acc = fmaf(hv.w, lg2(hv.w) - lg2(ev.w + c), acc);
    }

    // Reduce acc; tid0 finishes tile and atomically adds to out
#pragma unroll
    for (int o = 16; o > 0; o >>= 1) acc += __shfl_xor_sync(0xffffffffu, acc, o);
    if (lid == 0) wa[wid] = acc;
    __syncthreads();
    if (tid == 0) {
        const float v = ((wa[0] + wa[1]) + (wa[2] + wa[3]))
                      + ((wa[4] + wa[5]) + (wa[6] + wa[7]));
        // loss_tile = ln2 * (acc + lg2(S))   [sum(hm) == 1 per tile]
        atomicAdd(out, scale * (v + lg2(Sfull)));
    }
}

extern "C" void kernel_launch(void* const* d_in, const int* in_sizes, int n_in,
                              void* d_out, int out_size)
{
    const float*  hm    = (const float*)d_in[0];   // [B,P,H,W]
    const float2* means = (const float2*)d_in[1];  // [B,P,2]
    const float4* cov   = (const float4*)d_in[2];  // [B,P,4]
    float* out = (float*)d_out;

    const int n_bp = in_sizes[1] / 2;              // 4352

    cudaMemsetAsync(out, 0, (size_t)out_size * sizeof(float));
    gauss_kl_kernel<<<n_bp, NTHREADS>>>(hm, means, cov, out,
                                        LN2 / (float)n_bp);
}